// round 6
// baseline (speedup 1.0000x reference)
#include <cuda_runtime.h>
#include <math.h>

#define B 128

__device__ float g_h1[B * 1024];
__device__ float g_h2[B * 512];
__device__ float g_h3[B * 256];

__device__ __forceinline__ float ex2f(float x) {
    float y;
    asm("ex2.approx.f32 %0, %1;" : "=f"(y) : "f"(x));
    return y;
}

__device__ __forceinline__ float leaky_clamp01(float w) {
    float r = w;
    if (w < 0.0f)      r = 0.1f * w;
    else if (w > 1.0f) r = 1.0f + 0.1f * (w - 1.0f);
    return r;
}

__device__ __forceinline__ float tau_scale(const float* taup, float tau_floor) {
    float ta  = __ldg(taup);
    float tau = tau_floor + (ta >= 0.0f ? ta : 0.05f * ta);  // leaky_relu
    return tau * 1.4426950408889634f;                        // tau * log2(e)
}

// ============================================================================
// Unified layer kernel.
//   out[b,o] = 1 - (sum_i e^arg * arg)/(cs * sum_i e^arg), arg = cs*h[b,i]*aw[o,i]
// Tile: BT batch rows x OT outputs. K staged in KC chunks (KC=IN -> one chunk).
// S-way K split: thread (idx, s) covers [s*KC/S, (s+1)*KC/S) of every chunk;
// num/den are additive partials, reduced through smem at the end.
// CAT: layer-0 mode, h is x[B][IN/2], staged on the fly as concat(x, 1-x).
// ============================================================================
template <int IN, int BT, int OT, int KC, int S, bool CAT>
__global__ __launch_bounds__(BT * OT * S) void layer_kernel(
    const float* __restrict__ h, const float* __restrict__ W,
    const float* __restrict__ taup, float tau_floor,
    float* __restrict__ out, int out_dim) {
    constexpr int G   = BT * OT;      // outputs per block
    constexpr int T   = G * S;        // threads per block
    constexpr int KR  = KC / S;       // K range per thread per chunk
    constexpr int KCP = KC + 4;       // row pad: float4-aligned, bank-spread
    __shared__ float ch[BT * KCP];
    __shared__ float aw[OT * KCP];
    __shared__ float rnum[S > 1 ? T : 1];
    __shared__ float rden[S > 1 ? T : 1];

    const int tid   = threadIdx.x;
    const int obase = blockIdx.x * OT;
    const int bbase = blockIdx.y * BT;
    const int idx   = tid % G;
    const int s     = tid / G;
    const int b     = idx % BT;
    const int o     = idx / BT;

    const float cs = tau_scale(taup, tau_floor);

    float num = 0.0f, den = 0.0f;

    for (int k0 = 0; k0 < IN; k0 += KC) {
        if (k0) __syncthreads();
        {   // stage activations (fused concat(x,1-x) for layer 0)
            const bool inv  = CAT && (k0 >= IN / 2);
            const float sc  = inv ? -cs : cs;
            const float off = inv ?  cs : 0.0f;
            const int hk0   = CAT ? (k0 & (IN / 2 - 1)) : k0;
            const int hstr  = CAT ? (IN / 2) : IN;
            #pragma unroll
            for (int i = tid; i < BT * (KC / 4); i += T) {
                int bb = i / (KC / 4), kv = i - bb * (KC / 4);
                float4 v = *(const float4*)&h[(bbase + bb) * hstr + hk0 + kv * 4];
                float4 r;
                r.x = fmaf(v.x, sc, off); r.y = fmaf(v.y, sc, off);
                r.z = fmaf(v.z, sc, off); r.w = fmaf(v.w, sc, off);
                *(float4*)&ch[bb * KCP + kv * 4] = r;
            }
        }
        #pragma unroll
        for (int i = tid; i < OT * (KC / 4); i += T) {
            int oo = i / (KC / 4), kv = i - oo * (KC / 4);
            float4 v = *(const float4*)&W[(obase + oo) * IN + k0 + kv * 4];
            float4 r;
            r.x = leaky_clamp01(v.x); r.y = leaky_clamp01(v.y);
            r.z = leaky_clamp01(v.z); r.w = leaky_clamp01(v.w);
            *(float4*)&aw[oo * KCP + kv * 4] = r;
        }
        __syncthreads();

        const float* cp = &ch[b * KCP + s * KR];
        const float* ap = &aw[o * KCP + s * KR];
        #pragma unroll 4
        for (int k = 0; k < KR; k += 4) {
            float4 c = *(const float4*)&cp[k];
            float4 a = *(const float4*)&ap[k];
            float z;
            z = c.x * a.x; { float e = ex2f(z); den += e; num = fmaf(e, z, num); }
            z = c.y * a.y; { float e = ex2f(z); den += e; num = fmaf(e, z, num); }
            z = c.z * a.z; { float e = ex2f(z); den += e; num = fmaf(e, z, num); }
            z = c.w * a.w; { float e = ex2f(z); den += e; num = fmaf(e, z, num); }
        }
    }

    if (S > 1) {
        rnum[tid] = num;
        rden[tid] = den;
        __syncthreads();
        if (s == 0) {
            #pragma unroll
            for (int ss = 1; ss < S; ss++) {
                num += rnum[idx + ss * G];
                den += rden[idx + ss * G];
            }
            out[(bbase + b) * out_dim + obase + o] = 1.0f - (num / den) / cs;
        }
    } else {
        out[(bbase + b) * out_dim + obase + o] = 1.0f - (num / den) / cs;
    }
}

extern "C" void kernel_launch(void* const* d_in, const int* in_sizes, int n_in,
                              void* d_out, int out_size) {
    // metadata order: x, W0, tau0, W1, tau1, W2, tau2, W3, tau3
    const float* x  = (const float*)d_in[0];
    const float* W0 = (const float*)d_in[1];
    const float* t0 = (const float*)d_in[2];
    const float* W1 = (const float*)d_in[3];
    const float* t1 = (const float*)d_in[4];
    const float* W2 = (const float*)d_in[5];
    const float* t2 = (const float*)d_in[6];
    const float* W3 = (const float*)d_in[7];
    const float* t3 = (const float*)d_in[8];
    float* out = (float*)d_out;

    float *h1, *h2, *h3;
    cudaGetSymbolAddress((void**)&h1, g_h1);
    cudaGetSymbolAddress((void**)&h2, g_h2);
    cudaGetSymbolAddress((void**)&h3, g_h3);

    // tau_floor = log(in-1) + log(0.95/0.05)
    const float L19 = 2.9444389791664403f;
    const float tf0 = logf(1023.0f) + L19;
    const float tf1 = logf(1023.0f) + L19;
    const float tf2 = logf(511.0f)  + L19;
    const float tf3 = logf(255.0f)  + L19;

    // L0: 1024->1024, fused concat. 512 blocks x 512 thr = 8192 warps.
    layer_kernel<1024, 16, 16, 256, 2, true>
        <<<dim3(1024 / 16, B / 16), 16 * 16 * 2>>>(x, W0, t0, tf0, h1, 1024);
    // L1: 1024->512. 512 blocks x 256 thr = 4096 warps.
    layer_kernel<1024, 8, 16, 256, 2, false>
        <<<dim3(512 / 16, B / 8), 8 * 16 * 2>>>(h1, W1, t1, tf1, h2, 512);
    // L2: 512->256, single chunk, 4-way split. 512 blocks x 256 thr = 4096 warps.
    layer_kernel<512, 8, 8, 512, 4, false>
        <<<dim3(256 / 8, B / 8), 8 * 8 * 4>>>(h2, W2, t2, tf2, h3, 256);
    // L3: 256->128, single chunk, 8-way split. 512 blocks x 256 thr = 4096 warps.
    layer_kernel<256, 4, 8, 256, 8, false>
        <<<dim3(128 / 8, B / 4), 4 * 8 * 8>>>(h3, W3, t3, tf3, out, 128);
}